// round 10
// baseline (speedup 1.0000x reference)
#include <cuda_runtime.h>

#define PI_F 3.14159265358979323846f

// exact compile-time twiddles (roots of unity for N=12 and N=6)
#define SQ3_2 0.86602540378443864676f
static __device__ constexpr float CE12X[12] = {1.f, SQ3_2, .5f, 0.f, -.5f, -SQ3_2, -1.f, -SQ3_2, -.5f, 0.f, .5f, SQ3_2};
static __device__ constexpr float CE12Y[12] = {0.f, .5f, SQ3_2, 1.f, SQ3_2, .5f, 0.f, -.5f, -SQ3_2, -1.f, -SQ3_2, -.5f};
static __device__ constexpr float CE6X[6]   = {1.f, .5f, -.5f, -1.f, -.5f, .5f};
static __device__ constexpr float CE6Y[6]   = {0.f, SQ3_2, SQ3_2, 0.f, -SQ3_2, -SQ3_2};
__host__ __device__ constexpr int md(int x, int m) { return ((x % m) + m) % m; }

__constant__ float C_FACTF[11] = {1.f,1.f,2.f,6.f,24.f,120.f,720.f,5040.f,
                                  40320.f,362880.f,3628800.f};

__device__ float  g_w_l2[6];
__device__ float2 g_e20[20];
__device__ __align__(16) float  g_DS2 [1320];   // [l6][k20][m'+5]  (quad-weighted)
__device__ __align__(16) float  g_TD1C[5184];   // [l6][k12][mq6][j12 pad] *(2l+1), m'>=0 only
__device__ __align__(16) float  g_DSO3[900];    // [l3][k12][m2+2][p2+2] *w
__device__ __align__(16) float  g_TD2 [450];    // [l3][k6][m2+2][p2+2] *(2l+1)
__device__ __align__(16) float2 g_PSI1[1584];   // [l6][g24][m'+5]
__device__ __align__(16) float2 g_PSI2[10800];  // [l3][g144][m+2][p+2]
__device__ __align__(16) float2 g_CY1 [528];    // [l6][o8][p'+5]
__device__ __align__(16) float2 g_CY2 [9600];   // [l3][f8][o16][j2+2][k2+2]
__device__ float  g_feat[2048*16];
__device__ unsigned g_ctr;

__device__ float wig_df(int l, int mp, int m, float beta) {
    if (mp < -l || mp > l || m < -l || m > l) return 0.f;
    float c = cosf(0.5f*beta), s = sinf(0.5f*beta);
    int k0 = max(0, m - mp), k1 = min(l + m, l - mp);
    if (k1 < k0) return 0.f;
    float pre = sqrtf(C_FACTF[l+mp]*C_FACTF[l-mp]*C_FACTF[l+m]*C_FACTF[l-m]);
    float acc = 0.f;
    for (int k = k0; k <= k1; k++) {
        float t = pre/(C_FACTF[l+m-k]*C_FACTF[k]*C_FACTF[mp-m+k]*C_FACTF[l-mp-k]);
        int ec = 2*l - 2*k + m - mp, es = mp - m + 2*k;
        float pc = 1.f, ps = 1.f;
        for (int i = 0; i < ec; i++) pc *= c;
        for (int i = 0; i < es; i++) ps *= s;
        acc += (((mp - m + k) & 1) ? -t : t) * pc * ps;
    }
    return acc;
}

__device__ float quad_w(int k, int b) {   // Driscoll-Healy weight, fp32
    float beta = PI_F*(2*k+1)/(4.0f*b), ss = 0.f;
    for (int j = 0; j < b; j++) ss += sinf((2*j+1)*beta)/(float)(2*j+1);
    return (2.0f/b)*sinf(beta)*ss;
}

__global__ void k_tables() {
    const int N0=1320, N1=5184, N2=900, N3=450, N4=1584, N5=10800, N6=26;
    int stride = gridDim.x * blockDim.x;
    for (int e = blockIdx.x*blockDim.x + threadIdx.x; e < N0+N1+N2+N3+N4+N5+N6; e += stride) {
        int i = e;
        if (i < N0) {
            int j = i%11, k = (i/11)%20, l = i/220;
            g_DS2[i] = wig_df(l, j-5, 0, PI_F*(2*k+1)/40.0f) * quad_w(k, 10);
            continue;
        }
        i -= N0;
        if (i < N1) {  // TD1C[l][k][mq][j12]: m' = mq (0..5), m = j-5
            int j = i%12, mq = (i/12)%6, k = (i/72)%12, l = i/864;
            g_TD1C[i] = (j < 11) ? (float)(2*l+1)*wig_df(l, mq, j-5, PI_F*(2*k+1)/24.0f) : 0.f;
            continue;
        }
        i -= N1;
        if (i < N2) {
            int j = i%5, mi = (i/5)%5, k = (i/25)%12, l = i/300;
            g_DSO3[i] = wig_df(l, mi-2, j-2, PI_F*(2*k+1)/24.0f) * quad_w(k, 6);
            continue;
        }
        i -= N2;
        if (i < N3) {
            int j = i%5, mi = (i/5)%5, k = (i/25)%6, l = i/150;
            g_TD2[i] = (float)(2*l+1) * wig_df(l, mi-2, j-2, PI_F*(2*k+1)/12.0f);
            continue;
        }
        i -= N3;
        if (i < N4) {
            int j = i%11, g = (i/11)%24, l = i/264;
            int mp = j - 5;
            float b  = (float)(g/8 + 1) * (PI_F/24.0f);
            float al = (float)(g%8) * (PI_F/4.0f);
            float d  = wig_df(l, mp, 0, b);
            float ang = -(float)mp * al;
            g_PSI1[i] = make_float2(d*cosf(ang), d*sinf(ang));
            continue;
        }
        i -= N4;
        if (i < N5) {
            int j = i%5, mi = (i/5)%5, g = (i/25)%144, l = i/3600;
            int m = mi - 2, p = j - 2;
            float b  = (float)(g/48 + 1) * (PI_F/24.0f);
            float al = (float)((g/6)%8) * (PI_F/4.0f);
            float ga = (float)(g%6) * (PI_F/3.0f);
            float d  = wig_df(l, m, p, b);
            float ang = -((float)m*al + (float)p*ga);
            g_PSI2[i] = make_float2(d*cosf(ang), d*sinf(ang));
            continue;
        }
        i -= N5;
        if (i < 20)      { float a = 2.0f*PI_F*i/20.0f; g_e20[i] = make_float2(cosf(a), sinf(a)); }
        else             g_w_l2[i-20] = quad_w(i-20, 3);
    }
}

__global__ void k_weights(const float* __restrict__ w1, const float* __restrict__ w2) {
    const int NC1 = 528, NC2 = 9600;
    int stride = gridDim.x * blockDim.x;
    for (int e = blockIdx.x*blockDim.x + threadIdx.x; e < NC1+NC2; e += stride) {
        if (e < NC1) {
            int j = e%11, o = (e/11)%8, l = e/88;
            float re = 0.f, im = 0.f;
            for (int g = 0; g < 24; g++) {
                float wv = w1[o*24 + g];
                float2 ps = g_PSI1[(l*24 + g)*11 + j];
                re += wv*ps.x; im += wv*ps.y;
            }
            g_CY1[e] = make_float2(re, -im);
        } else {
            int i = e - NC1;
            int k2 = i%5, j2 = (i/5)%5, o = (i/25)%16, f = (i/400)%8, l = i/3200;
            float re = 0.f, im = 0.f;
            for (int g = 0; g < 144; g++) {
                float wv = w2[(f*16 + o)*144 + g];
                float2 ps = g_PSI2[((l*144 + g)*5 + j2)*5 + k2];
                re += wv*ps.x; im += wv*ps.y;
            }
            g_CY2[i] = make_float2(re, -im);
        }
    }
}

__device__ __forceinline__ float2 cfma(float2 a, float2 b, float2 c) {
    c.x += a.x*b.x - a.y*b.y;
    c.y += a.x*b.y + a.y*b.x;
    return c;
}
__device__ __forceinline__ void cfmac(float2 f, float wx, float wy, float2& c) {
    c.x += f.x*wx - f.y*wy;
    c.y += f.x*wy + f.y*wx;
}

#define SM_FLOATS (256 + 2*13824)
#define SM_BYTES  (SM_FLOATS*4)

__global__ void __launch_bounds__(512, 2)
k_forward(const float* __restrict__ x, const float* __restrict__ b1,
          const float* __restrict__ b2, const float* __restrict__ w_out,
          const float* __restrict__ b_out, float* __restrict__ out) {
    extern __shared__ float sm[];
    float2* se20 = (float2*)(sm);        // 20c
    float*  sb1  = sm + 76;              // 8
    float*  sb2  = sm + 84;              // 16
    float*  swi  = sm + 100;             // 6
    float2* sXS  = (float2*)(sm + 108);  // 66c
    float*  A    = sm + 256;
    float*  Bb   = sm + 256 + 13824;
    __shared__ unsigned s_last;

    const int tid = threadIdx.x;
    const int n = blockIdx.x;

    if (tid < 20)                se20[tid]     = g_e20[tid];
    if (tid >= 96  && tid < 104) sb1 [tid-96]  = b1[tid-96];
    if (tid >= 128 && tid < 144) sb2 [tid-128] = b2[tid-128];
    if (tid >= 160 && tid < 166) swi [tid-160] = g_w_l2[tid-160] * (1.f/36.f);

    // Ph0: load x[n] (20x20) into A[0..400)
    float* sx = A;
    for (int i = tid; i < 400; i += 512) sx[i] = x[n*400 + i];
    __syncthreads();

    // Ph1: alpha analysis Xf[k][m'+5] (B). Idle threads stage TD1C into A[6912..12096).
    float2* Xf = (float2*)Bb;
    float* sTD1 = A + 6912;
    if (tid < 220) {
        int k = tid/11, mp = tid%11 - 5;
        int s = (20 - mp) % 20;
        const float* xp = sx + k*20;
        float re = 0.f, im = 0.f;
        int r = 0;
        #pragma unroll
        for (int a = 0; a < 20; a++) {
            float v = xp[a];
            float2 w = se20[r];
            re += v*w.x; im += v*w.y;
            r += s; if (r >= 20) r -= 20;
        }
        Xf[tid] = make_float2(re, im);
    } else if (tid >= 256) {
        float4* dst = (float4*)sTD1;
        const float4* src = (const float4*)g_TD1C;
        for (int i = tid - 256; i < 1296; i += 256) dst[i] = src[i];
    }
    __syncthreads();

    // Ph2: XS[l][m'+5] = sum_k DS2 * Xf
    if (tid < 66) {
        int l = tid/11, j = tid%11;
        float2 acc = make_float2(0.f, 0.f);
        #pragma unroll
        for (int k = 0; k < 20; k++) {
            float d = g_DS2[(l*20 + k)*11 + j];
            float2 v = Xf[k*11 + j];
            acc.x += d*v.x; acc.y += d*v.y;
        }
        sXS[tid] = acc;
    }
    __syncthreads();

    // Ph3: P[l][o][mq][j12 pad] = XS * CY1   (A[0..6912))
    float2* P = (float2*)A;
    if (tid < 288) {
        int mq = tid % 6, o = (tid/6) % 8, l = tid/48;
        float2 xs = sXS[l*11 + mq + 5];
        const float2* cy = g_CY1 + (l*8 + o)*11;
        float2* op = P + ((l*8 + o)*6 + mq)*12;
        #pragma unroll
        for (int j = 0; j < 11; j++) {
            float2 c = cy[j];
            op[j] = make_float2(xs.x*c.x - xs.y*c.y, xs.x*c.y + xs.y*c.x);
        }
        op[11] = make_float2(0.f, 0.f);
    }
    __syncthreads();

    // Ph4+5 fused: jacc[j] = sum_{l>=mq} TD1C*P (regs), radix-2 gamma synthesis -> G (B)
    // mq = t/96 is warp-uniform (96 = 3 warps) -> runtime l-loop skips l<mq (zeros).
    float2* G = (float2*)Bb;
    for (int t = tid; t < 576; t += 512) {
        int mq = t / 96;
        int r  = t % 96;
        int o  = r / 12, kk = r % 12;
        float2 jacc[12];
        #pragma unroll
        for (int j = 0; j < 12; j++) jacc[j] = make_float2(0.f, 0.f);
        for (int l = mq; l < 6; l++) {
            const float4* dp4 = (const float4*)(sTD1 + ((l*12 + kk)*6 + mq)*12);
            const float4* pp4 = (const float4*)(P + ((l*8 + o)*6 + mq)*12);
            #pragma unroll
            for (int q = 0; q < 3; q++) {
                float4 d  = dp4[q];
                float4 pa = pp4[2*q], pb = pp4[2*q+1];
                jacc[4*q+0].x += d.x*pa.x; jacc[4*q+0].y += d.x*pa.y;
                jacc[4*q+1].x += d.y*pa.z; jacc[4*q+1].y += d.y*pa.w;
                jacc[4*q+2].x += d.z*pb.x; jacc[4*q+2].y += d.z*pb.y;
                jacc[4*q+3].x += d.w*pb.z; jacc[4*q+3].y += d.w*pb.w;
            }
        }
        float2* gp = G + ((o*12 + kk)*6 + mq)*12;
        #pragma unroll
        for (int g1 = 0; g1 < 6; g1++) {
            float2 Se = make_float2(0.f, 0.f), So = make_float2(0.f, 0.f);
            #pragma unroll
            for (int j = 1; j < 11; j += 2)   // p' even
                cfmac(jacc[j], CE12X[md((j-5)*g1,12)], CE12Y[md((j-5)*g1,12)], Se);
            #pragma unroll
            for (int j = 0; j < 11; j += 2)   // p' odd
                cfmac(jacc[j], CE12X[md((j-5)*g1,12)], CE12Y[md((j-5)*g1,12)], So);
            gp[g1]     = make_float2(Se.x + So.x, Se.y + So.y);
            gp[g1 + 6] = make_float2(Se.x - So.x, Se.y - So.y);
        }
    }
    __syncthreads();

    // Ph6: alpha synthesis (Hermitian, radix-2) + bias + ReLU -> h1[f][k][a][g] (A)
    float* h1 = A;
    for (int t = tid; t < 1152; t += 512) {
        int g = t % 12, kk = (t/12) % 12, f = t/144;
        const float2* Gp = G + (f*12 + kk)*72 + g;
        float2 gm1 = Gp[12], gm2 = Gp[24], gm3 = Gp[36], gm4 = Gp[48], gm5 = Gp[60];
        float g0 = Gp[0].x;
        float bb = sb1[f];
        float* op = h1 + ((f*12 + kk)*12)*12 + g;
        #pragma unroll
        for (int a1 = 0; a1 < 6; a1++) {
            float E = g0
                + 2.f*(gm2.x*CE12X[md(2*a1,12)] - gm2.y*CE12Y[md(2*a1,12)])
                + 2.f*(gm4.x*CE12X[md(4*a1,12)] - gm4.y*CE12Y[md(4*a1,12)]);
            float O =
                  2.f*(gm1.x*CE12X[md(a1,12)]   - gm1.y*CE12Y[md(a1,12)])
                + 2.f*(gm3.x*CE12X[md(3*a1,12)] - gm3.y*CE12Y[md(3*a1,12)])
                + 2.f*(gm5.x*CE12X[md(5*a1,12)] - gm5.y*CE12Y[md(5*a1,12)]);
            op[a1*12]       = fmaxf(E + O + bb, 0.f);
            op[(a1 + 6)*12] = fmaxf(E - O + bb, 0.f);
        }
    }
    __syncthreads();

    // Ph7: gamma analysis T[f][k][a][p2] (B). Radix-2 in g.
    float2* T = (float2*)Bb;
    for (int t = tid; t < 1152; t += 512) {
        int a = t % 12, kk = (t/12) % 12, f = t/144;
        const float4* hp4 = (const float4*)(h1 + ((f*12 + kk)*12 + a)*12);
        float h[12];
        #pragma unroll
        for (int q = 0; q < 3; q++) {
            float4 v = hp4[q];
            h[4*q] = v.x; h[4*q+1] = v.y; h[4*q+2] = v.z; h[4*q+3] = v.w;
        }
        float he[6], ho[6];
        #pragma unroll
        for (int g1 = 0; g1 < 6; g1++) { he[g1] = h[g1] + h[g1+6]; ho[g1] = h[g1] - h[g1+6]; }
        float2* op = T + ((f*12 + kk)*12 + a)*3;
        op[0] = make_float2(he[0]+he[1]+he[2]+he[3]+he[4]+he[5], 0.f);
        {
            float re = 0.f, im = 0.f;
            #pragma unroll
            for (int g1 = 0; g1 < 6; g1++) {
                re += ho[g1]*CE12X[g1];
                im -= ho[g1]*CE12Y[g1];
            }
            op[1] = make_float2(re, im);
        }
        {
            float re = 0.f, im = 0.f;
            #pragma unroll
            for (int g1 = 0; g1 < 6; g1++) {
                re += he[g1]*CE12X[md(2*g1,12)];
                im -= he[g1]*CE12Y[md(2*g1,12)];
            }
            op[2] = make_float2(re, im);
        }
    }
    __syncthreads();

    // Ph8: alpha analysis F2h[f][k][m2+2][p2+2] (A), m2 = 0..2, radix-2 in a.
    // m2 = tid/96 is warp-uniform -> compile-time immediate twiddles per branch.
    // twiddle(a) = e^{-i m2 a 2pi/12}; tw(a1+6) = tw(a1)*(-1)^{m2}.
    float2* F2h = (float2*)A;
    if (tid < 288) {
        int m2 = tid / 96;
        int r  = tid % 96;
        int f = r / 12, kk = r % 12;
        const float2* Tp = T + ((f*12 + kk)*12)*3;
        float2 acc[5];
        #pragma unroll
        for (int j = 0; j < 5; j++) acc[j] = make_float2(0.f, 0.f);
        if (m2 == 0) {
            #pragma unroll
            for (int a1 = 0; a1 < 6; a1++) {
                float2 t0 = Tp[a1*3+0], t1 = Tp[a1*3+1], t2 = Tp[a1*3+2];
                float2 u0 = Tp[(a1+6)*3+0], u1 = Tp[(a1+6)*3+1], u2 = Tp[(a1+6)*3+2];
                t0.x += u0.x; t0.y += u0.y;
                t1.x += u1.x; t1.y += u1.y;
                t2.x += u2.x; t2.y += u2.y;
                acc[0].x += t2.x; acc[0].y -= t2.y;
                acc[1].x += t1.x; acc[1].y -= t1.y;
                acc[2].x += t0.x; acc[2].y += t0.y;
                acc[3].x += t1.x; acc[3].y += t1.y;
                acc[4].x += t2.x; acc[4].y += t2.y;
            }
        } else if (m2 == 1) {
            #pragma unroll
            for (int a1 = 0; a1 < 6; a1++) {
                float2 t0 = Tp[a1*3+0], t1 = Tp[a1*3+1], t2 = Tp[a1*3+2];
                float2 u0 = Tp[(a1+6)*3+0], u1 = Tp[(a1+6)*3+1], u2 = Tp[(a1+6)*3+2];
                t0.x -= u0.x; t0.y -= u0.y;
                t1.x -= u1.x; t1.y -= u1.y;
                t2.x -= u2.x; t2.y -= u2.y;
                const float wx = CE12X[md(-a1,12)], wy = CE12Y[md(-a1,12)];
                cfmac(make_float2(t2.x, -t2.y), wx, wy, acc[0]);
                cfmac(make_float2(t1.x, -t1.y), wx, wy, acc[1]);
                cfmac(t0, wx, wy, acc[2]);
                cfmac(t1, wx, wy, acc[3]);
                cfmac(t2, wx, wy, acc[4]);
            }
        } else {
            #pragma unroll
            for (int a1 = 0; a1 < 6; a1++) {
                float2 t0 = Tp[a1*3+0], t1 = Tp[a1*3+1], t2 = Tp[a1*3+2];
                float2 u0 = Tp[(a1+6)*3+0], u1 = Tp[(a1+6)*3+1], u2 = Tp[(a1+6)*3+2];
                t0.x += u0.x; t0.y += u0.y;
                t1.x += u1.x; t1.y += u1.y;
                t2.x += u2.x; t2.y += u2.y;
                const float wx = CE12X[md(-2*a1,12)], wy = CE12Y[md(-2*a1,12)];
                cfmac(make_float2(t2.x, -t2.y), wx, wy, acc[0]);
                cfmac(make_float2(t1.x, -t1.y), wx, wy, acc[1]);
                cfmac(t0, wx, wy, acc[2]);
                cfmac(t1, wx, wy, acc[3]);
                cfmac(t2, wx, wy, acc[4]);
            }
        }
        float2* op = F2h + ((f*12 + kk)*5 + (m2+2))*5;
        #pragma unroll
        for (int j = 0; j < 5; j++) op[j] = acc[j];
    }
    __syncthreads();

    // Ph9: XS2[l][f][i2][k2] = sum_k F2h * DSO3   (B), one output per thread (360)
    float2* XS2 = (float2*)Bb;
    if (tid < 360) {
        int k2 = tid % 5;
        int rr = tid / 5;
        int i2 = rr % 3 + 2, f = (rr/3) % 8, l = rr/24;
        float2 acc = make_float2(0.f, 0.f);
        #pragma unroll
        for (int k = 0; k < 12; k++) {
            float d = g_DSO3[((l*12 + k)*5 + i2)*5 + k2];
            float2 v = F2h[((f*12 + k)*5 + i2)*5 + k2];
            acc.x += d*v.x; acc.y += d*v.y;
        }
        XS2[(l*8 + f)*25 + i2*5 + k2] = acc;
    }
    __syncthreads();

    // Ph10: Z2[l][o][i2][j2] (A), i2 = 2..4. 2 units of 15 lanes per warp,
    // k2-sum in-register -> no shuffles, no idle-lane FMA.
    float2* Z2 = (float2*)A;
    {
        int w = tid >> 5, lane = tid & 31;
        int half = lane >> 4;          // unit within warp
        int sl = lane & 15;            // 0..15; 15 idle
        int q = sl / 5, j2 = sl % 5;   // q = i2-2
        #pragma unroll
        for (int it = 0; it < 2; it++) {
            int unit = it*32 + w*2 + half;    // 0..63
            if (unit < 48 && sl < 15) {
                int l = unit >> 4, o = unit & 15;
                float2 acc = make_float2(0.f, 0.f);
                #pragma unroll
                for (int f = 0; f < 8; f++) {
                    const float2* xb = XS2 + (l*8 + f)*25 + (q+2)*5;
                    const float2* cp = g_CY2 + (((l*8 + f)*16 + o)*5 + j2)*5;
                    #pragma unroll
                    for (int k2 = 0; k2 < 5; k2++)
                        acc = cfma(xb[k2], cp[k2], acc);
                }
                Z2[((l*16 + o)*5 + (q+2))*5 + j2] = acc;
            }
        }
    }
    __syncthreads();

    // Ph11 fused: jacc = sum_{l>=mq} TD2*Z2 (regs), radix-2 gamma synthesis -> G2 (B)
    float2* G2 = (float2*)Bb;
    if (tid < 288) {
        int mq = tid / 96;
        int r  = tid % 96;
        int o  = r / 6, kk = r % 6;
        float2 jacc[5];
        #pragma unroll
        for (int j = 0; j < 5; j++) jacc[j] = make_float2(0.f, 0.f);
        for (int l = mq; l < 3; l++) {
            const float* dp = g_TD2 + ((l*6 + kk)*5 + (mq+2))*5;
            const float2* zp = Z2 + ((l*16 + o)*5 + (mq+2))*5;
            #pragma unroll
            for (int j = 0; j < 5; j++) {
                float d = dp[j];
                jacc[j].x += d*zp[j].x; jacc[j].y += d*zp[j].y;
            }
        }
        float2* gp = G2 + ((o*6 + kk)*3 + mq)*6;
        #pragma unroll
        for (int g1 = 0; g1 < 3; g1++) {
            float2 Se = make_float2(0.f, 0.f), So = make_float2(0.f, 0.f);
            cfmac(jacc[0], CE6X[md(-2*g1,6)], CE6Y[md(-2*g1,6)], Se);
            Se.x += jacc[2].x; Se.y += jacc[2].y;
            cfmac(jacc[4], CE6X[md(2*g1,6)], CE6Y[md(2*g1,6)], Se);
            cfmac(jacc[1], CE6X[md(-g1,6)], CE6Y[md(-g1,6)], So);
            cfmac(jacc[3], CE6X[md(g1,6)],  CE6Y[md(g1,6)],  So);
            gp[g1]     = make_float2(Se.x + So.x, Se.y + So.y);
            gp[g1 + 3] = make_float2(Se.x - So.x, Se.y - So.y);
        }
    }
    __syncthreads();

    // Ph12: alpha synthesis (Hermitian) + bias + ReLU, pre-weighted -> h2 (A)
    float* h2 = A;
    for (int t = tid; t < 576; t += 512) {
        int g = t % 6, kk = (t/6) % 6, o = t/36;
        const float2* Gp = G2 + (o*6 + kk)*18 + g;
        float2 g0 = Gp[0], g1 = Gp[6], g2 = Gp[12];
        float g1x = 2.f*g1.x, g1y = 2.f*g1.y, g2x = 2.f*g2.x, g2y = 2.f*g2.y;
        float bb = sb2[o];
        float wk = swi[kk];
        float* op = h2 + ((o*6 + kk)*6)*6 + g;
        #pragma unroll
        for (int a = 0; a < 6; a++) {
            float v = g0.x + g1x*CE6X[md(a,6)] - g1y*CE6Y[md(a,6)]
                           + g2x*CE6X[md(2*a,6)] - g2y*CE6Y[md(2*a,6)];
            op[a*6] = fmaxf(v + bb, 0.f) * wk;
        }
    }
    __syncthreads();

    // Ph13: integrate: feat[n][o] = sum over pre-weighted h2
    {
        int w = tid >> 5, lane = tid & 31;
        const float* hp = h2 + w*216;
        float s = 0.f;
        #pragma unroll
        for (int idx = lane; idx < 216; idx += 32)
            s += hp[idx];
        #pragma unroll
        for (int off = 16; off; off >>= 1)
            s += __shfl_down_sync(0xffffffffu, s, off);
        if (lane == 0) g_feat[n*16 + w] = s;
    }

    // Fused final: last CTA does maxpool + linear
    __threadfence();
    __syncthreads();
    if (tid == 0) {
        unsigned old = atomicAdd(&g_ctr, 1u);
        s_last = (old == (unsigned)(gridDim.x - 1)) ? 1u : 0u;
    }
    __syncthreads();
    if (s_last) {
        __threadfence();
        float* sp = A;
        float* pooled = A + 512;
        for (int b = 0; b < 4; b++) {
            int o = tid & 15, grp = tid >> 4;
            float m = -3.4e38f;
            #pragma unroll
            for (int j = 0; j < 16; j++) {
                int p = grp + j*32;
                m = fmaxf(m, g_feat[(b*512 + p)*16 + o]);
            }
            sp[grp*16 + o] = m;
            __syncthreads();
            if (tid < 16) {
                float mm = sp[tid];
                for (int g2 = 1; g2 < 32; g2++) mm = fmaxf(mm, sp[g2*16 + tid]);
                pooled[tid] = mm;
            }
            __syncthreads();
            if (tid < 10) {
                float acc = b_out[tid];
                #pragma unroll
                for (int o2 = 0; o2 < 16; o2++) acc += pooled[o2]*w_out[tid*16 + o2];
                out[b*10 + tid] = acc;
            }
            __syncthreads();
        }
        if (tid == 0) g_ctr = 0;
    }
}

extern "C" void kernel_launch(void* const* d_in, const int* in_sizes, int n_in,
                              void* d_out, int out_size) {
    const float* x     = (const float*)d_in[0];
    const float* w1    = (const float*)d_in[1];
    const float* b1    = (const float*)d_in[2];
    const float* w2    = (const float*)d_in[3];
    const float* b2    = (const float*)d_in[4];
    const float* w_out = (const float*)d_in[5];
    const float* b_out = (const float*)d_in[6];
    float* out = (float*)d_out;

    cudaFuncSetAttribute(k_forward, cudaFuncAttributeMaxDynamicSharedMemorySize, SM_BYTES);

    k_tables<<<48, 512>>>();
    k_weights<<<20, 512>>>(w1, w2);
    k_forward<<<2048, 512, SM_BYTES>>>(x, b1, b2, w_out, b_out, out);
}